// round 15
// baseline (speedup 1.0000x reference)
#include <cuda_runtime.h>
#include <cuda_fp16.h>
#include <cstdint>

// ============================================================================
// Axial attention, persistent CTAs (296 = 2/SM), fused per-(b,h) tile.
// HMMA fp16 split: QK 3-pass (K=32 stages), Vproj 1-pass (K=64 stages),
// AV 1-pass. 3-stage cp.async ring, continuous ACROSS tiles (48 % 3 == 0).
// B=16, C=512, C8=64, H=W=64.
// ============================================================================

#define NT 256
#define NSLOT 296
#define NTILE 1024
#define SWB(o)  ((o) ^ (((o) >> 3) & 0x70))   // 128B-pitch swizzle
#define SW64(o) ((o) ^ (((o) >> 3) & 0x30))   // 64B-pitch swizzle

// pre-split weights (fp16 hi/lo): rows 0-63 Wq, 64-127 Wk, 128-639 Wv
__device__ __half g_wh[640 * 512];
__device__ __half g_wl[640 * 512];
// pre-split x (fp16 hi/lo), reordered to [b][h][c][w]  (tile = b*64+h)
__device__ __half g_xh[16u * 64 * 512 * 64];
__device__ __half g_xl[16u * 64 * 512 * 64];

// SMEM layout (byte offsets from 1KB-aligned base):
//  ring: 3 stages x 24576.
//   QK stage (g<16):  +0 Whi[128][64B] SW64 (8K) | +8192 Wlo (8K)
//                     +16384 Xhi[32][128B] SW128 (4K) | +20480 Xlo (4K)
//   V stage (g>=16):  +0 Whi[128][128B] SW128 (16K) | +16384 Xhi[64][128B] (8K)
//  C:  73728 : Qs fp32 [64][64] | VH fp16 [128][128B] (16K)
//      90112 : Ks fp32 [64][64]
//  P:  106496: PH fp16 [64][128B] (8K)
#define STAGE 24576
#define Co    73728
#define PHo   106496
#define SMEM_BYTES (114688 + 1024)

__device__ __forceinline__ uint32_t smem_u32(const void* p) {
    uint32_t a;
    asm("{ .reg .u64 t; cvta.to.shared.u64 t, %1; cvt.u32.u64 %0, t; }"
        : "=r"(a) : "l"(p));
    return a;
}
__device__ __forceinline__ void cpasync16(uint32_t dst, const void* src) {
    asm volatile("cp.async.cg.shared.global [%0], [%1], 16;" :: "r"(dst), "l"(src));
}
__device__ __forceinline__ void cpcommit() {
    asm volatile("cp.async.commit_group;" ::: "memory");
}
__device__ __forceinline__ void cpwait1() {
    asm volatile("cp.async.wait_group 1;" ::: "memory");
}
__device__ __forceinline__ void cpwait0() {
    asm volatile("cp.async.wait_group 0;" ::: "memory");
}
__device__ __forceinline__ void ldsm_x4(uint32_t addr, uint32_t r[4]) {
    asm volatile("ldmatrix.sync.aligned.m8n8.x4.shared.b16 {%0,%1,%2,%3}, [%4];"
                 : "=r"(r[0]), "=r"(r[1]), "=r"(r[2]), "=r"(r[3]) : "r"(addr));
}
__device__ __forceinline__ void ldsm_x4t(uint32_t addr, uint32_t r[4]) {
    asm volatile("ldmatrix.sync.aligned.m8n8.x4.trans.shared.b16 {%0,%1,%2,%3}, [%4];"
                 : "=r"(r[0]), "=r"(r[1]), "=r"(r[2]), "=r"(r[3]) : "r"(addr));
}
__device__ __forceinline__ void mma_f16(float d[4], const uint32_t a[4],
                                        uint32_t b0, uint32_t b1) {
    asm volatile(
        "mma.sync.aligned.m16n8k16.row.col.f32.f16.f16.f32 "
        "{%0,%1,%2,%3}, {%4,%5,%6,%7}, {%8,%9}, {%0,%1,%2,%3};"
        : "+f"(d[0]), "+f"(d[1]), "+f"(d[2]), "+f"(d[3])
        : "r"(a[0]), "r"(a[1]), "r"(a[2]), "r"(a[3]), "r"(b0), "r"(b1));
}
// fp32 pair -> packed fp16 hi / lo (element a in low half)
__device__ __forceinline__ void split2(float a, float b, unsigned& hi, unsigned& lo) {
    __half ha = __float2half_rn(a), hb = __float2half_rn(b);
    float la = a - __half2float(ha);
    float lb = b - __half2float(hb);
    hi = (unsigned)__half_as_ushort(ha) | ((unsigned)__half_as_ushort(hb) << 16);
    lo = (unsigned)__half_as_ushort(__float2half_rn(la))
       | ((unsigned)__half_as_ushort(__float2half_rn(lb)) << 16);
}
__device__ __forceinline__ unsigned pack_half2(float a, float b) {
    return (unsigned)__half_as_ushort(__float2half_rn(a))
         | ((unsigned)__half_as_ushort(__float2half_rn(b)) << 16);
}

// A-fragment addr, 128B-pitch SW128
__device__ __forceinline__ uint32_t faddrA(uint32_t region, int row0, int colB, int lane) {
    int row = row0 + (lane & 7) + ((lane >> 3) & 1) * 8;
    int cb  = colB + ((lane >> 4) << 4);
    return region + SWB(row * 128 + cb);
}
// A-fragment addr, 64B-pitch SW64 (QK W buffers)
__device__ __forceinline__ uint32_t faddrW(uint32_t region, int row0, int colB, int lane) {
    int row = row0 + (lane & 7) + ((lane >> 3) & 1) * 8;
    int cb  = colB + ((lane >> 4) << 4);
    return region + SW64(row * 64 + cb);
}
// P as B (non-trans), 128B pitch
__device__ __forceinline__ uint32_t faddrP(uint32_t region, int w0, int kB, int lane) {
    int row = w0 + (lane & 7) + ((lane >> 4) << 3);
    int cb  = kB + ((lane >> 3) & 1) * 16;
    return region + SWB(row * 128 + cb);
}

// ---------------------------------------------------------------------------
// merged prologue: blocks [0,32768) split x ; [32768,33088) split W
// ---------------------------------------------------------------------------
__global__ void __launch_bounds__(256, 4)
prep_kernel(const float* __restrict__ x,
            const float* __restrict__ Wq, const float* __restrict__ Wk,
            const float* __restrict__ Wv)
{
    if (blockIdx.x >= 32768) {
        int gid = (blockIdx.x - 32768) * 256 + threadIdx.x;    // 81920 float4s
        int r = gid >> 7;
        int c = (gid & 127) * 4;
        const float* src = (r < 64)  ? (Wq + (size_t)r * 512 + c)
                         : (r < 128) ? (Wk + (size_t)(r - 64) * 512 + c)
                                     : (Wv + (size_t)(r - 128) * 512 + c);
        float4 v = *(const float4*)src;
        unsigned h0, l0, h1, l1;
        split2(v.x, v.y, h0, l0);
        split2(v.z, v.w, h1, l1);
        size_t off = (size_t)r * 512 + c;
        *(uint2*)(g_wh + off) = make_uint2(h0, h1);
        *(uint2*)(g_wl + off) = make_uint2(l0, l1);
    } else {
        size_t gid = (size_t)blockIdx.x * 256 + threadIdx.x;   // 8388608 float4s
        int w4 = (int)(gid & 15);
        size_t r = gid >> 4;
        int hh  = (int)(r & 63);
        size_t bc = r >> 6;
        int c  = (int)(bc & 511);
        int b  = (int)(bc >> 9);
        float4 v = *(const float4*)(x + gid * 4);
        unsigned h0, l0, h1, l1;
        split2(v.x, v.y, h0, l0);
        split2(v.z, v.w, h1, l1);
        size_t off = (((size_t)b * 64 + hh) * 512 + c) * 64 + w4 * 4;
        *(uint2*)(g_xh + off) = make_uint2(h0, h1);
        *(uint2*)(g_xl + off) = make_uint2(l0, l1);
    }
}

// ---------------------------------------------------------------------------
// issue stage g (0..47) of a given tile; ring slot = g % 3 (continuous
// across tiles since 48 % 3 == 0)
__device__ __forceinline__ void issueStage(uint32_t sb, int tile, int g, int t) {
    const __half* xh = g_xh + (size_t)tile * 32768;
    const __half* xl = g_xl + (size_t)tile * 32768;
    uint32_t stage = sb + (g % 3) * STAGE;
    if (g < 16) {
        int c0 = g * 32;
        #pragma unroll
        for (int j = t; j < 1024; j += NT) {        // W: 128 rows x 64B, hi+lo
            int half = j >> 9;
            int u    = j & 511;
            int row  = u >> 2;
            int seg  = u & 3;
            const __half* src =
                (half ? g_wl : g_wh) + (size_t)row * 512 + c0 + seg * 8;
            cpasync16(stage + half * 8192 + SW64(row * 64 + seg * 16), src);
        }
        #pragma unroll
        for (int j = t; j < 512; j += NT) {         // X hi+lo: 32 rows x 128B
            int half = j >> 8;
            int u    = j & 255;
            int row  = u >> 3;
            int seg  = u & 7;
            const __half* src = (half ? xl : xh) + (size_t)(c0 + row) * 64 + seg * 8;
            cpasync16(stage + 16384 + half * 4096 + SWB(row * 128 + seg * 16), src);
        }
    } else {
        int local = g - 16;
        int Rb = 128 + (local >> 3) * 128;
        int c0 = (local & 7) * 64;
        #pragma unroll
        for (int j = t; j < 1024; j += NT) {        // Whi: 128 rows x 128B
            int row = j >> 3;
            int seg = j & 7;
            cpasync16(stage + SWB(row * 128 + seg * 16),
                      g_wh + (size_t)(Rb + row) * 512 + c0 + seg * 8);
        }
        #pragma unroll
        for (int j = t; j < 512; j += NT) {         // Xhi: 64 rows x 128B
            int row = j >> 3;
            int seg = j & 7;
            cpasync16(stage + 16384 + SWB(row * 128 + seg * 16),
                      xh + (size_t)(c0 + row) * 64 + seg * 8);
        }
    }
    cpcommit();
}

// QK chunk (K=32), 3-pass fragment-reuse
__device__ __forceinline__ void mma_chunk_qk(uint32_t stage, int m0, int nB, int lane,
                                             float acc[2][4][4]) {
    uint32_t Xh = stage + 16384, Xl = stage + 20480;
    #pragma unroll
    for (int ks = 0; ks < 2; ks++) {
        uint32_t bH0[4], bH1[4], bL0[4], bL1[4], a[4];
        ldsm_x4t(faddrA(Xh, ks * 16, nB,      lane), bH0);
        ldsm_x4t(faddrA(Xh, ks * 16, nB + 32, lane), bH1);
        ldsm_x4t(faddrA(Xl, ks * 16, nB,      lane), bL0);
        ldsm_x4t(faddrA(Xl, ks * 16, nB + 32, lane), bL1);

        ldsm_x4(faddrW(stage, m0, ks * 32, lane), a);              // W hi, m0
        mma_f16(acc[0][0], a, bH0[0], bH0[1]);
        mma_f16(acc[0][1], a, bH0[2], bH0[3]);
        mma_f16(acc[0][2], a, bH1[0], bH1[1]);
        mma_f16(acc[0][3], a, bH1[2], bH1[3]);
        mma_f16(acc[0][0], a, bL0[0], bL0[1]);
        mma_f16(acc[0][1], a, bL0[2], bL0[3]);
        mma_f16(acc[0][2], a, bL1[0], bL1[1]);
        mma_f16(acc[0][3], a, bL1[2], bL1[3]);

        ldsm_x4(faddrW(stage, m0 + 16, ks * 32, lane), a);         // W hi, m0+16
        mma_f16(acc[1][0], a, bH0[0], bH0[1]);
        mma_f16(acc[1][1], a, bH0[2], bH0[3]);
        mma_f16(acc[1][2], a, bH1[0], bH1[1]);
        mma_f16(acc[1][3], a, bH1[2], bH1[3]);
        mma_f16(acc[1][0], a, bL0[0], bL0[1]);
        mma_f16(acc[1][1], a, bL0[2], bL0[3]);
        mma_f16(acc[1][2], a, bL1[0], bL1[1]);
        mma_f16(acc[1][3], a, bL1[2], bL1[3]);

        ldsm_x4(faddrW(stage + 8192, m0, ks * 32, lane), a);       // W lo, m0
        mma_f16(acc[0][0], a, bH0[0], bH0[1]);
        mma_f16(acc[0][1], a, bH0[2], bH0[3]);
        mma_f16(acc[0][2], a, bH1[0], bH1[1]);
        mma_f16(acc[0][3], a, bH1[2], bH1[3]);

        ldsm_x4(faddrW(stage + 8192, m0 + 16, ks * 32, lane), a);  // W lo, m0+16
        mma_f16(acc[1][0], a, bH0[0], bH0[1]);
        mma_f16(acc[1][1], a, bH0[2], bH0[3]);
        mma_f16(acc[1][2], a, bH1[0], bH1[1]);
        mma_f16(acc[1][3], a, bH1[2], bH1[3]);
    }
}

// V chunk (K=64), 1-pass: Whi x Xhi
__device__ __forceinline__ void mma_chunk_v64(uint32_t stage, int m0, int nB, int lane,
                                              float acc[2][4][4]) {
    uint32_t Xh = stage + 16384;
    #pragma unroll
    for (int ks = 0; ks < 4; ks++) {
        uint32_t bH0[4], bH1[4], a[4];
        ldsm_x4t(faddrA(Xh, ks * 16, nB,      lane), bH0);
        ldsm_x4t(faddrA(Xh, ks * 16, nB + 32, lane), bH1);

        ldsm_x4(faddrA(stage, m0, ks * 32, lane), a);
        mma_f16(acc[0][0], a, bH0[0], bH0[1]);
        mma_f16(acc[0][1], a, bH0[2], bH0[3]);
        mma_f16(acc[0][2], a, bH1[0], bH1[1]);
        mma_f16(acc[0][3], a, bH1[2], bH1[3]);

        ldsm_x4(faddrA(stage, m0 + 16, ks * 32, lane), a);
        mma_f16(acc[1][0], a, bH0[0], bH0[1]);
        mma_f16(acc[1][1], a, bH0[2], bH0[3]);
        mma_f16(acc[1][2], a, bH1[0], bH1[1]);
        mma_f16(acc[1][3], a, bH1[2], bH1[3]);
    }
}

// ---------------------------------------------------------------------------
// main persistent kernel: grid 296, 256 threads, 2 CTAs/SM
// ---------------------------------------------------------------------------
extern "C" __global__ void __launch_bounds__(NT, 2)
axial_attn_kernel(const float* __restrict__ bq, const float* __restrict__ bk,
                  const float* __restrict__ bv,
                  const float* __restrict__ relh, const float* __restrict__ relw,
                  float* __restrict__ out)
{
    extern __shared__ char smraw[];
    char* smb = (char*)(((uintptr_t)smraw + 1023) & ~(uintptr_t)1023);
    const uint32_t sb = smem_u32(smb);

    const uint32_t PH = sb + PHo;
    const uint32_t VH = sb + Co;
    float* Qs = (float*)(smb + Co);
    float* Ks = (float*)(smb + Co + 16384);

    const int t    = threadIdx.x;
    const int wid  = t >> 5;
    const int lane = t & 31;
    const int m0   = (wid >> 1) * 32;
    const int wn   = wid & 1;
    const int nB   = wn * 64;

    // bootstrap ring with first tile's stages 0,1
    issueStage(sb, blockIdx.x, 0, t);
    issueStage(sb, blockIdx.x, 1, t);

    for (int tile = blockIdx.x; tile < NTILE; tile += NSLOT) {
        const int hRow = tile & 63;
        const int b    = tile >> 6;
        const bool lastTile = (tile + NSLOT >= NTILE);

        // ---- Phase 1: QK projection, stages 0..15 ----
        float acc[2][4][4];
        #pragma unroll
        for (int i = 0; i < 2; i++)
            #pragma unroll
            for (int j = 0; j < 4; j++)
                #pragma unroll
                for (int e = 0; e < 4; e++) acc[i][j][e] = 0.f;

        for (int g = 0; g < 16; g++) {
            cpwait1();
            __syncthreads();
            issueStage(sb, tile, g + 2, t);
            mma_chunk_qk(sb + (g % 3) * STAGE, m0, nB, lane, acc);
        }

        // epilogue: bias + rel -> Qs / Ks fp32
        #pragma unroll
        for (int mi = 0; mi < 2; mi++) {
            #pragma unroll
            for (int nj = 0; nj < 4; nj++) {
                int row = m0 + mi * 16 + (lane >> 2);
                int col = wn * 32 + nj * 8 + (lane & 3) * 2;
                float d0 = acc[mi][nj][0], d1 = acc[mi][nj][1];
                float d2 = acc[mi][nj][2], d3 = acc[mi][nj][3];
                if (row < 64) {
                    float a  = bq[row] + relh[(size_t)row * 512 + hRow];
                    float a2 = bq[row + 8] + relh[(size_t)(row + 8) * 512 + hRow];
                    *(float2*)&Qs[row * 64 + col]       = make_float2(d0 + a,  d1 + a);
                    *(float2*)&Qs[(row + 8) * 64 + col] = make_float2(d2 + a2, d3 + a2);
                } else {
                    int ok = row - 64;
                    float b1 = bk[ok], b2 = bk[ok + 8];
                    *(float2*)&Ks[ok * 64 + col] = make_float2(
                        d0 + b1 + relw[(size_t)ok * 512 + col],
                        d1 + b1 + relw[(size_t)ok * 512 + col + 1]);
                    *(float2*)&Ks[(ok + 8) * 64 + col] = make_float2(
                        d2 + b2 + relw[(size_t)(ok + 8) * 512 + col],
                        d3 + b2 + relw[(size_t)(ok + 8) * 512 + col + 1]);
                }
            }
        }
        __syncthreads();

        // ---- Phase 2+3: scores + softmax in registers -> P fp16 ----
        {
            int sv = (t & 15) * 4;
            int sw = (t >> 4) * 4;
            float s[4][4];
            #pragma unroll
            for (int i = 0; i < 4; i++)
                #pragma unroll
                for (int j = 0; j < 4; j++) s[i][j] = 0.f;
            #pragma unroll 4
            for (int c = 0; c < 64; c++) {
                float4 kv = *(const float4*)&Ks[c * 64 + sv];
                float4 qv = *(const float4*)&Qs[c * 64 + sw];
                float q[4] = {qv.x, qv.y, qv.z, qv.w};
                #pragma unroll
                for (int i = 0; i < 4; i++) {
                    s[i][0] += q[i] * kv.x; s[i][1] += q[i] * kv.y;
                    s[i][2] += q[i] * kv.z; s[i][3] += q[i] * kv.w;
                }
            }
            #pragma unroll
            for (int i = 0; i < 4; i++) {
                float m = fmaxf(fmaxf(s[i][0], s[i][1]), fmaxf(s[i][2], s[i][3]));
                #pragma unroll
                for (int off = 8; off > 0; off >>= 1)
                    m = fmaxf(m, __shfl_xor_sync(0xffffffffu, m, off));
                float e0 = __expf(s[i][0] - m), e1 = __expf(s[i][1] - m);
                float e2 = __expf(s[i][2] - m), e3 = __expf(s[i][3] - m);
                float tt = e0 + e1 + e2 + e3;
                #pragma unroll
                for (int off = 8; off > 0; off >>= 1)
                    tt += __shfl_xor_sync(0xffffffffu, tt, off);
                float inv = 1.f / tt;
                unsigned ha = pack_half2(e0 * inv, e1 * inv);
                unsigned hb = pack_half2(e2 * inv, e3 * inv);
                int off = SWB((sw + i) * 128 + sv * 2);
                *(uint2*)(smb + PHo + off) = make_uint2(ha, hb);
            }
        }

        // ---- Phase 4: V projection (K=64 stages) + AV, stages 16..47 ----
        for (int g = 16; g < 48; g++) {
            int local = g - 16;
            int kc = local & 7;
            if (kc == 0) {
                float* va = &acc[0][0][0];
                #pragma unroll
                for (int i = 0; i < 32; i++) va[i] = 0.f;
            }
            if (lastTile && g == 47) cpwait0(); else cpwait1();
            __syncthreads();
            {
                int n = g + 2;
                if (n < 48)        issueStage(sb, tile, n, t);
                else if (!lastTile) issueStage(sb, tile + NSLOT, n - 48, t);
            }
            mma_chunk_v64(sb + (g % 3) * STAGE, m0, nB, lane, acc);

            if (kc == 7) {
                int dc = local >> 3;
                // epilogue: +bias -> VH fp16 [d][v]
                #pragma unroll
                for (int mi = 0; mi < 2; mi++) {
                    #pragma unroll
                    for (int nj = 0; nj < 4; nj++) {
                        int row = m0 + mi * 16 + (lane >> 2);
                        int col = wn * 32 + nj * 8 + (lane & 3) * 2;
                        float b0f = bv[dc * 128 + row];
                        float b1f = bv[dc * 128 + row + 8];
                        unsigned h0 = pack_half2(acc[mi][nj][0] + b0f, acc[mi][nj][1] + b0f);
                        unsigned h1 = pack_half2(acc[mi][nj][2] + b1f, acc[mi][nj][3] + b1f);
                        *(unsigned*)(smb + Co + SWB(row * 128 + col * 2))       = h0;
                        *(unsigned*)(smb + Co + SWB((row + 8) * 128 + col * 2)) = h1;
                    }
                }
                __syncthreads();

                // AV 1-pass: out[d][w] = sum_v VH[d][v] PH[w][v]
                float oac[2][4][4];
                #pragma unroll
                for (int i = 0; i < 2; i++)
                    #pragma unroll
                    for (int j = 0; j < 4; j++)
                        #pragma unroll
                        for (int e = 0; e < 4; e++) oac[i][j][e] = 0.f;

                #pragma unroll
                for (int k = 0; k < 4; k++) {
                    uint32_t p0h[4], p1h[4], a[4];
                    ldsm_x4(faddrP(PH, wn * 32,      k * 32, lane), p0h);
                    ldsm_x4(faddrP(PH, wn * 32 + 16, k * 32, lane), p1h);

                    ldsm_x4(faddrA(VH, m0, k * 32, lane), a);
                    mma_f16(oac[0][0], a, p0h[0], p0h[1]);
                    mma_f16(oac[0][1], a, p0h[2], p0h[3]);
                    mma_f16(oac[0][2], a, p1h[0], p1h[1]);
                    mma_f16(oac[0][3], a, p1h[2], p1h[3]);

                    ldsm_x4(faddrA(VH, m0 + 16, k * 32, lane), a);
                    mma_f16(oac[1][0], a, p0h[0], p0h[1]);
                    mma_f16(oac[1][1], a, p0h[2], p0h[3]);
                    mma_f16(oac[1][2], a, p1h[0], p1h[1]);
                    mma_f16(oac[1][3], a, p1h[2], p1h[3]);
                }

                #pragma unroll
                for (int mi = 0; mi < 2; mi++) {
                    #pragma unroll
                    for (int nj = 0; nj < 4; nj++) {
                        int row = m0 + mi * 16 + (lane >> 2);
                        int col = wn * 32 + nj * 8 + (lane & 3) * 2;
                        size_t base0 = (((size_t)b * 512 + dc * 128 + row) * 64 + hRow) * 64 + col;
                        size_t base1 = base0 + 8 * 4096;
                        *(float2*)&out[base0] = make_float2(oac[mi][nj][0], oac[mi][nj][1]);
                        *(float2*)&out[base1] = make_float2(oac[mi][nj][2], oac[mi][nj][3]);
                    }
                }
            }
        }
    }
}

extern "C" void kernel_launch(void* const* d_in, const int* in_sizes, int n_in,
                              void* d_out, int out_size)
{
    const float* x    = (const float*)d_in[0];
    const float* Wq   = (const float*)d_in[1];
    const float* bq   = (const float*)d_in[2];
    const float* Wk   = (const float*)d_in[3];
    const float* bk   = (const float*)d_in[4];
    const float* Wv   = (const float*)d_in[5];
    const float* bv   = (const float*)d_in[6];
    const float* relh = (const float*)d_in[7];
    const float* relw = (const float*)d_in[8];
    float* out = (float*)d_out;

    cudaFuncSetAttribute(axial_attn_kernel,
                         cudaFuncAttributeMaxDynamicSharedMemorySize, SMEM_BYTES);

    prep_kernel<<<33088, 256>>>(x, Wq, Wk, Wv);
    axial_attn_kernel<<<NSLOT, NT, SMEM_BYTES>>>(bq, bk, bv, relh, relw, out);
}

// round 16
// speedup vs baseline: 1.0050x; 1.0050x over previous
#include <cuda_runtime.h>
#include <cuda_fp16.h>
#include <cstdint>

// ============================================================================
// Axial attention, persistent CTAs (296 = 2/SM), fused per-(b,h) tile.
// HMMA fp16 split: QK 3-pass (K=32 stages), Vproj 1-pass (K=64 stages),
// AV 1-pass. 3-stage cp.async ring, continuous ACROSS tiles (48 % 3 == 0).
// B=16, C=512, C8=64, H=W=64.
// ============================================================================

#define NT 256
#define NSLOT 296
#define NTILE 1024
#define SWB(o)  ((o) ^ (((o) >> 3) & 0x70))   // 128B-pitch swizzle
#define SW64(o) ((o) ^ (((o) >> 3) & 0x30))   // 64B-pitch swizzle

// pre-split weights (fp16 hi/lo): rows 0-63 Wq, 64-127 Wk, 128-639 Wv
__device__ __half g_wh[640 * 512];
__device__ __half g_wl[640 * 512];
// pre-split x (fp16 hi/lo), reordered to [b][h][c][w]  (tile = b*64+h)
__device__ __half g_xh[16u * 64 * 512 * 64];
__device__ __half g_xl[16u * 64 * 512 * 64];

// SMEM layout (byte offsets from 1KB-aligned base):
//  ring: 3 stages x 24576.
//   QK stage (g<16):  +0 Whi[128][64B] SW64 (8K) | +8192 Wlo (8K)
//                     +16384 Xhi[32][128B] SW128 (4K) | +20480 Xlo (4K)
//   V stage (g>=16):  +0 Whi[128][128B] SW128 (16K) | +16384 Xhi[64][128B] (8K)
//  C:  73728 : Qs fp32 [64][64] | VH fp16 [128][128B] (16K)
//      90112 : Ks fp32 [64][64]
//  P:  106496: PH fp16 [64][128B] (8K)
#define STAGE 24576
#define Co    73728
#define PHo   106496
#define SMEM_BYTES (114688 + 1024)

__device__ __forceinline__ uint32_t smem_u32(const void* p) {
    uint32_t a;
    asm("{ .reg .u64 t; cvta.to.shared.u64 t, %1; cvt.u32.u64 %0, t; }"
        : "=r"(a) : "l"(p));
    return a;
}
__device__ __forceinline__ void cpasync16(uint32_t dst, const void* src) {
    asm volatile("cp.async.cg.shared.global [%0], [%1], 16;" :: "r"(dst), "l"(src));
}
__device__ __forceinline__ void cpcommit() {
    asm volatile("cp.async.commit_group;" ::: "memory");
}
__device__ __forceinline__ void cpwait1() {
    asm volatile("cp.async.wait_group 1;" ::: "memory");
}
__device__ __forceinline__ void cpwait0() {
    asm volatile("cp.async.wait_group 0;" ::: "memory");
}
__device__ __forceinline__ void ldsm_x4(uint32_t addr, uint32_t r[4]) {
    asm volatile("ldmatrix.sync.aligned.m8n8.x4.shared.b16 {%0,%1,%2,%3}, [%4];"
                 : "=r"(r[0]), "=r"(r[1]), "=r"(r[2]), "=r"(r[3]) : "r"(addr));
}
__device__ __forceinline__ void ldsm_x4t(uint32_t addr, uint32_t r[4]) {
    asm volatile("ldmatrix.sync.aligned.m8n8.x4.trans.shared.b16 {%0,%1,%2,%3}, [%4];"
                 : "=r"(r[0]), "=r"(r[1]), "=r"(r[2]), "=r"(r[3]) : "r"(addr));
}
__device__ __forceinline__ void mma_f16(float d[4], const uint32_t a[4],
                                        uint32_t b0, uint32_t b1) {
    asm volatile(
        "mma.sync.aligned.m16n8k16.row.col.f32.f16.f16.f32 "
        "{%0,%1,%2,%3}, {%4,%5,%6,%7}, {%8,%9}, {%0,%1,%2,%3};"
        : "+f"(d[0]), "+f"(d[1]), "+f"(d[2]), "+f"(d[3])
        : "r"(a[0]), "r"(a[1]), "r"(a[2]), "r"(a[3]), "r"(b0), "r"(b1));
}
// fp32 pair -> packed fp16 hi / lo (element a in low half)
__device__ __forceinline__ void split2(float a, float b, unsigned& hi, unsigned& lo) {
    __half ha = __float2half_rn(a), hb = __float2half_rn(b);
    float la = a - __half2float(ha);
    float lb = b - __half2float(hb);
    hi = (unsigned)__half_as_ushort(ha) | ((unsigned)__half_as_ushort(hb) << 16);
    lo = (unsigned)__half_as_ushort(__float2half_rn(la))
       | ((unsigned)__half_as_ushort(__float2half_rn(lb)) << 16);
}
__device__ __forceinline__ unsigned pack_half2(float a, float b) {
    return (unsigned)__half_as_ushort(__float2half_rn(a))
         | ((unsigned)__half_as_ushort(__float2half_rn(b)) << 16);
}

// A-fragment addr, 128B-pitch SW128
__device__ __forceinline__ uint32_t faddrA(uint32_t region, int row0, int colB, int lane) {
    int row = row0 + (lane & 7) + ((lane >> 3) & 1) * 8;
    int cb  = colB + ((lane >> 4) << 4);
    return region + SWB(row * 128 + cb);
}
// A-fragment addr, 64B-pitch SW64 (QK W buffers)
__device__ __forceinline__ uint32_t faddrW(uint32_t region, int row0, int colB, int lane) {
    int row = row0 + (lane & 7) + ((lane >> 3) & 1) * 8;
    int cb  = colB + ((lane >> 4) << 4);
    return region + SW64(row * 64 + cb);
}
// P as B (non-trans), 128B pitch
__device__ __forceinline__ uint32_t faddrP(uint32_t region, int w0, int kB, int lane) {
    int row = w0 + (lane & 7) + ((lane >> 4) << 3);
    int cb  = kB + ((lane >> 3) & 1) * 16;
    return region + SWB(row * 128 + cb);
}

// ---------------------------------------------------------------------------
// merged prologue: blocks [0,32768) split x ; [32768,33088) split W
// ---------------------------------------------------------------------------
__global__ void __launch_bounds__(256, 4)
prep_kernel(const float* __restrict__ x,
            const float* __restrict__ Wq, const float* __restrict__ Wk,
            const float* __restrict__ Wv)
{
    if (blockIdx.x >= 32768) {
        int gid = (blockIdx.x - 32768) * 256 + threadIdx.x;    // 81920 float4s
        int r = gid >> 7;
        int c = (gid & 127) * 4;
        const float* src = (r < 64)  ? (Wq + (size_t)r * 512 + c)
                         : (r < 128) ? (Wk + (size_t)(r - 64) * 512 + c)
                                     : (Wv + (size_t)(r - 128) * 512 + c);
        float4 v = *(const float4*)src;
        unsigned h0, l0, h1, l1;
        split2(v.x, v.y, h0, l0);
        split2(v.z, v.w, h1, l1);
        size_t off = (size_t)r * 512 + c;
        *(uint2*)(g_wh + off) = make_uint2(h0, h1);
        *(uint2*)(g_wl + off) = make_uint2(l0, l1);
    } else {
        size_t gid = (size_t)blockIdx.x * 256 + threadIdx.x;   // 8388608 float4s
        int w4 = (int)(gid & 15);
        size_t r = gid >> 4;
        int hh  = (int)(r & 63);
        size_t bc = r >> 6;
        int c  = (int)(bc & 511);
        int b  = (int)(bc >> 9);
        float4 v = *(const float4*)(x + gid * 4);
        unsigned h0, l0, h1, l1;
        split2(v.x, v.y, h0, l0);
        split2(v.z, v.w, h1, l1);
        size_t off = (((size_t)b * 64 + hh) * 512 + c) * 64 + w4 * 4;
        *(uint2*)(g_xh + off) = make_uint2(h0, h1);
        *(uint2*)(g_xl + off) = make_uint2(l0, l1);
    }
}

// ---------------------------------------------------------------------------
// issue stage g (0..47) of a given tile; ring slot = g % 3 (continuous
// across tiles since 48 % 3 == 0)
__device__ __forceinline__ void issueStage(uint32_t sb, int tile, int g, int t) {
    const __half* xh = g_xh + (size_t)tile * 32768;
    const __half* xl = g_xl + (size_t)tile * 32768;
    uint32_t stage = sb + (g % 3) * STAGE;
    if (g < 16) {
        int c0 = g * 32;
        #pragma unroll
        for (int j = t; j < 1024; j += NT) {        // W: 128 rows x 64B, hi+lo
            int half = j >> 9;
            int u    = j & 511;
            int row  = u >> 2;
            int seg  = u & 3;
            const __half* src =
                (half ? g_wl : g_wh) + (size_t)row * 512 + c0 + seg * 8;
            cpasync16(stage + half * 8192 + SW64(row * 64 + seg * 16), src);
        }
        #pragma unroll
        for (int j = t; j < 512; j += NT) {         // X hi+lo: 32 rows x 128B
            int half = j >> 8;
            int u    = j & 255;
            int row  = u >> 3;
            int seg  = u & 7;
            const __half* src = (half ? xl : xh) + (size_t)(c0 + row) * 64 + seg * 8;
            cpasync16(stage + 16384 + half * 4096 + SWB(row * 128 + seg * 16), src);
        }
    } else {
        int local = g - 16;
        int Rb = 128 + (local >> 3) * 128;
        int c0 = (local & 7) * 64;
        #pragma unroll
        for (int j = t; j < 1024; j += NT) {        // Whi: 128 rows x 128B
            int row = j >> 3;
            int seg = j & 7;
            cpasync16(stage + SWB(row * 128 + seg * 16),
                      g_wh + (size_t)(Rb + row) * 512 + c0 + seg * 8);
        }
        #pragma unroll
        for (int j = t; j < 512; j += NT) {         // Xhi: 64 rows x 128B
            int row = j >> 3;
            int seg = j & 7;
            cpasync16(stage + 16384 + SWB(row * 128 + seg * 16),
                      xh + (size_t)(c0 + row) * 64 + seg * 8);
        }
    }
    cpcommit();
}

// QK chunk (K=32), 3-pass fragment-reuse
__device__ __forceinline__ void mma_chunk_qk(uint32_t stage, int m0, int nB, int lane,
                                             float acc[2][4][4]) {
    uint32_t Xh = stage + 16384, Xl = stage + 20480;
    #pragma unroll
    for (int ks = 0; ks < 2; ks++) {
        uint32_t bH0[4], bH1[4], bL0[4], bL1[4], a[4];
        ldsm_x4t(faddrA(Xh, ks * 16, nB,      lane), bH0);
        ldsm_x4t(faddrA(Xh, ks * 16, nB + 32, lane), bH1);
        ldsm_x4t(faddrA(Xl, ks * 16, nB,      lane), bL0);
        ldsm_x4t(faddrA(Xl, ks * 16, nB + 32, lane), bL1);

        ldsm_x4(faddrW(stage, m0, ks * 32, lane), a);              // W hi, m0
        mma_f16(acc[0][0], a, bH0[0], bH0[1]);
        mma_f16(acc[0][1], a, bH0[2], bH0[3]);
        mma_f16(acc[0][2], a, bH1[0], bH1[1]);
        mma_f16(acc[0][3], a, bH1[2], bH1[3]);
        mma_f16(acc[0][0], a, bL0[0], bL0[1]);
        mma_f16(acc[0][1], a, bL0[2], bL0[3]);
        mma_f16(acc[0][2], a, bL1[0], bL1[1]);
        mma_f16(acc[0][3], a, bL1[2], bL1[3]);

        ldsm_x4(faddrW(stage, m0 + 16, ks * 32, lane), a);         // W hi, m0+16
        mma_f16(acc[1][0], a, bH0[0], bH0[1]);
        mma_f16(acc[1][1], a, bH0[2], bH0[3]);
        mma_f16(acc[1][2], a, bH1[0], bH1[1]);
        mma_f16(acc[1][3], a, bH1[2], bH1[3]);
        mma_f16(acc[1][0], a, bL0[0], bL0[1]);
        mma_f16(acc[1][1], a, bL0[2], bL0[3]);
        mma_f16(acc[1][2], a, bL1[0], bL1[1]);
        mma_f16(acc[1][3], a, bL1[2], bL1[3]);

        ldsm_x4(faddrW(stage + 8192, m0, ks * 32, lane), a);       // W lo, m0
        mma_f16(acc[0][0], a, bH0[0], bH0[1]);
        mma_f16(acc[0][1], a, bH0[2], bH0[3]);
        mma_f16(acc[0][2], a, bH1[0], bH1[1]);
        mma_f16(acc[0][3], a, bH1[2], bH1[3]);

        ldsm_x4(faddrW(stage + 8192, m0 + 16, ks * 32, lane), a);  // W lo, m0+16
        mma_f16(acc[1][0], a, bH0[0], bH0[1]);
        mma_f16(acc[1][1], a, bH0[2], bH0[3]);
        mma_f16(acc[1][2], a, bH1[0], bH1[1]);
        mma_f16(acc[1][3], a, bH1[2], bH1[3]);
    }
}

// V chunk (K=64), 1-pass: Whi x Xhi
__device__ __forceinline__ void mma_chunk_v64(uint32_t stage, int m0, int nB, int lane,
                                              float acc[2][4][4]) {
    uint32_t Xh = stage + 16384;
    #pragma unroll
    for (int ks = 0; ks < 4; ks++) {
        uint32_t bH0[4], bH1[4], a[4];
        ldsm_x4t(faddrA(Xh, ks * 16, nB,      lane), bH0);
        ldsm_x4t(faddrA(Xh, ks * 16, nB + 32, lane), bH1);

        ldsm_x4(faddrA(stage, m0, ks * 32, lane), a);
        mma_f16(acc[0][0], a, bH0[0], bH0[1]);
        mma_f16(acc[0][1], a, bH0[2], bH0[3]);
        mma_f16(acc[0][2], a, bH1[0], bH1[1]);
        mma_f16(acc[0][3], a, bH1[2], bH1[3]);

        ldsm_x4(faddrA(stage, m0 + 16, ks * 32, lane), a);
        mma_f16(acc[1][0], a, bH0[0], bH0[1]);
        mma_f16(acc[1][1], a, bH0[2], bH0[3]);
        mma_f16(acc[1][2], a, bH1[0], bH1[1]);
        mma_f16(acc[1][3], a, bH1[2], bH1[3]);
    }
}

// ---------------------------------------------------------------------------
// main persistent kernel: grid 296, 256 threads, 2 CTAs/SM
// ---------------------------------------------------------------------------
extern "C" __global__ void __launch_bounds__(NT, 2)
axial_attn_kernel(const float* __restrict__ bq, const float* __restrict__ bk,
                  const float* __restrict__ bv,
                  const float* __restrict__ relh, const float* __restrict__ relw,
                  float* __restrict__ out)
{
    extern __shared__ char smraw[];
    char* smb = (char*)(((uintptr_t)smraw + 1023) & ~(uintptr_t)1023);
    const uint32_t sb = smem_u32(smb);

    const uint32_t PH = sb + PHo;
    const uint32_t VH = sb + Co;
    float* Qs = (float*)(smb + Co);
    float* Ks = (float*)(smb + Co + 16384);

    const int t    = threadIdx.x;
    const int wid  = t >> 5;
    const int lane = t & 31;
    const int m0   = (wid >> 1) * 32;
    const int wn   = wid & 1;
    const int nB   = wn * 64;

    // bootstrap ring with first tile's stages 0,1
    issueStage(sb, blockIdx.x, 0, t);
    issueStage(sb, blockIdx.x, 1, t);

    for (int tile = blockIdx.x; tile < NTILE; tile += NSLOT) {
        const int hRow = tile & 63;
        const int b    = tile >> 6;
        const bool lastTile = (tile + NSLOT >= NTILE);

        // ---- Phase 1: QK projection, stages 0..15 ----
        float acc[2][4][4];
        #pragma unroll
        for (int i = 0; i < 2; i++)
            #pragma unroll
            for (int j = 0; j < 4; j++)
                #pragma unroll
                for (int e = 0; e < 4; e++) acc[i][j][e] = 0.f;

        for (int g = 0; g < 16; g++) {
            cpwait1();
            __syncthreads();
            issueStage(sb, tile, g + 2, t);
            mma_chunk_qk(sb + (g % 3) * STAGE, m0, nB, lane, acc);
        }

        // epilogue: bias + rel -> Qs / Ks fp32
        #pragma unroll
        for (int mi = 0; mi < 2; mi++) {
            #pragma unroll
            for (int nj = 0; nj < 4; nj++) {
                int row = m0 + mi * 16 + (lane >> 2);
                int col = wn * 32 + nj * 8 + (lane & 3) * 2;
                float d0 = acc[mi][nj][0], d1 = acc[mi][nj][1];
                float d2 = acc[mi][nj][2], d3 = acc[mi][nj][3];
                if (row < 64) {
                    float a  = bq[row] + relh[(size_t)row * 512 + hRow];
                    float a2 = bq[row + 8] + relh[(size_t)(row + 8) * 512 + hRow];
                    *(float2*)&Qs[row * 64 + col]       = make_float2(d0 + a,  d1 + a);
                    *(float2*)&Qs[(row + 8) * 64 + col] = make_float2(d2 + a2, d3 + a2);
                } else {
                    int ok = row - 64;
                    float b1 = bk[ok], b2 = bk[ok + 8];
                    *(float2*)&Ks[ok * 64 + col] = make_float2(
                        d0 + b1 + relw[(size_t)ok * 512 + col],
                        d1 + b1 + relw[(size_t)ok * 512 + col + 1]);
                    *(float2*)&Ks[(ok + 8) * 64 + col] = make_float2(
                        d2 + b2 + relw[(size_t)(ok + 8) * 512 + col],
                        d3 + b2 + relw[(size_t)(ok + 8) * 512 + col + 1]);
                }
            }
        }
        __syncthreads();

        // ---- Phase 2+3: scores + softmax in registers -> P fp16 ----
        {
            int sv = (t & 15) * 4;
            int sw = (t >> 4) * 4;
            float s[4][4];
            #pragma unroll
            for (int i = 0; i < 4; i++)
                #pragma unroll
                for (int j = 0; j < 4; j++) s[i][j] = 0.f;
            #pragma unroll 4
            for (int c = 0; c < 64; c++) {
                float4 kv = *(const float4*)&Ks[c * 64 + sv];
                float4 qv = *(const float4*)&Qs[c * 64 + sw];
                float q[4] = {qv.x, qv.y, qv.z, qv.w};
                #pragma unroll
                for (int i = 0; i < 4; i++) {
                    s[i][0] += q[i] * kv.x; s[i][1] += q[i] * kv.y;
                    s[i][2] += q[i] * kv.z; s[i][3] += q[i] * kv.w;
                }
            }
            #pragma unroll
            for (int i = 0; i < 4; i++) {
                float m = fmaxf(fmaxf(s[i][0], s[i][1]), fmaxf(s[i][2], s[i][3]));
                #pragma unroll
                for (int off = 8; off > 0; off >>= 1)
                    m = fmaxf(m, __shfl_xor_sync(0xffffffffu, m, off));
                float e0 = __expf(s[i][0] - m), e1 = __expf(s[i][1] - m);
                float e2 = __expf(s[i][2] - m), e3 = __expf(s[i][3] - m);
                float tt = e0 + e1 + e2 + e3;
                #pragma unroll
                for (int off = 8; off > 0; off >>= 1)
                    tt += __shfl_xor_sync(0xffffffffu, tt, off);
                float inv = 1.f / tt;
                unsigned ha = pack_half2(e0 * inv, e1 * inv);
                unsigned hb = pack_half2(e2 * inv, e3 * inv);
                int off = SWB((sw + i) * 128 + sv * 2);
                *(uint2*)(smb + PHo + off) = make_uint2(ha, hb);
            }
        }

        // ---- Phase 4: V projection (K=64 stages) + AV, stages 16..47 ----
        for (int g = 16; g < 48; g++) {
            int local = g - 16;
            int kc = local & 7;
            if (kc == 0) {
                float* va = &acc[0][0][0];
                #pragma unroll
                for (int i = 0; i < 32; i++) va[i] = 0.f;
            }
            if (lastTile && g == 47) cpwait0(); else cpwait1();
            __syncthreads();
            {
                int n = g + 2;
                if (n < 48)        issueStage(sb, tile, n, t);
                else if (!lastTile) issueStage(sb, tile + NSLOT, n - 48, t);
            }
            mma_chunk_v64(sb + (g % 3) * STAGE, m0, nB, lane, acc);

            if (kc == 7) {
                int dc = local >> 3;
                // epilogue: +bias -> VH fp16 [d][v]
                #pragma unroll
                for (int mi = 0; mi < 2; mi++) {
                    #pragma unroll
                    for (int nj = 0; nj < 4; nj++) {
                        int row = m0 + mi * 16 + (lane >> 2);
                        int col = wn * 32 + nj * 8 + (lane & 3) * 2;
                        float b0f = bv[dc * 128 + row];
                        float b1f = bv[dc * 128 + row + 8];
                        unsigned h0 = pack_half2(acc[mi][nj][0] + b0f, acc[mi][nj][1] + b0f);
                        unsigned h1 = pack_half2(acc[mi][nj][2] + b1f, acc[mi][nj][3] + b1f);
                        *(unsigned*)(smb + Co + SWB(row * 128 + col * 2))       = h0;
                        *(unsigned*)(smb + Co + SWB((row + 8) * 128 + col * 2)) = h1;
                    }
                }
                __syncthreads();

                // AV 1-pass: out[d][w] = sum_v VH[d][v] PH[w][v]
                float oac[2][4][4];
                #pragma unroll
                for (int i = 0; i < 2; i++)
                    #pragma unroll
                    for (int j = 0; j < 4; j++)
                        #pragma unroll
                        for (int e = 0; e < 4; e++) oac[i][j][e] = 0.f;

                #pragma unroll
                for (int k = 0; k < 4; k++) {
                    uint32_t p0h[4], p1h[4], a[4];
                    ldsm_x4(faddrP(PH, wn * 32,      k * 32, lane), p0h);
                    ldsm_x4(faddrP(PH, wn * 32 + 16, k * 32, lane), p1h);

                    ldsm_x4(faddrA(VH, m0, k * 32, lane), a);
                    mma_f16(oac[0][0], a, p0h[0], p0h[1]);
                    mma_f16(oac[0][1], a, p0h[2], p0h[3]);
                    mma_f16(oac[0][2], a, p1h[0], p1h[1]);
                    mma_f16(oac[0][3], a, p1h[2], p1h[3]);

                    ldsm_x4(faddrA(VH, m0 + 16, k * 32, lane), a);
                    mma_f16(oac[1][0], a, p0h[0], p0h[1]);
                    mma_f16(oac[1][1], a, p0h[2], p0h[3]);
                    mma_f16(oac[1][2], a, p1h[0], p1h[1]);
                    mma_f16(oac[1][3], a, p1h[2], p1h[3]);
                }

                #pragma unroll
                for (int mi = 0; mi < 2; mi++) {
                    #pragma unroll
                    for (int nj = 0; nj < 4; nj++) {
                        int row = m0 + mi * 16 + (lane >> 2);
                        int col = wn * 32 + nj * 8 + (lane & 3) * 2;
                        size_t base0 = (((size_t)b * 512 + dc * 128 + row) * 64 + hRow) * 64 + col;
                        size_t base1 = base0 + 8 * 4096;
                        *(float2*)&out[base0] = make_float2(oac[mi][nj][0], oac[mi][nj][1]);
                        *(float2*)&out[base1] = make_float2(oac[mi][nj][2], oac[mi][nj][3]);
                    }
                }
            }
        }
    }
}

extern "C" void kernel_launch(void* const* d_in, const int* in_sizes, int n_in,
                              void* d_out, int out_size)
{
    const float* x    = (const float*)d_in[0];
    const float* Wq   = (const float*)d_in[1];
    const float* bq   = (const float*)d_in[2];
    const float* Wk   = (const float*)d_in[3];
    const float* bk   = (const float*)d_in[4];
    const float* Wv   = (const float*)d_in[5];
    const float* bv   = (const float*)d_in[6];
    const float* relh = (const float*)d_in[7];
    const float* relw = (const float*)d_in[8];
    float* out = (float*)d_out;

    cudaFuncSetAttribute(axial_attn_kernel,
                         cudaFuncAttributeMaxDynamicSharedMemorySize, SMEM_BYTES);

    prep_kernel<<<33088, 256>>>(x, Wq, Wk, Wv);
    axial_attn_kernel<<<NSLOT, NT, SMEM_BYTES>>>(bq, bk, bv, relh, relw, out);
}

// round 17
// speedup vs baseline: 1.0143x; 1.0092x over previous
#include <cuda_runtime.h>
#include <cuda_fp16.h>
#include <cstdint>

// ============================================================================
// Axial attention, persistent CTAs (296 = 2/SM), fused per-(b,h) tile.
// HMMA fp16 split: QK 3-pass (K=32 stages), scores 3-pass HMMA,
// Vproj 1-pass (K=64 stages), AV 1-pass. 3-stage cp.async ring,
// continuous ACROSS tiles (48 % 3 == 0).
// B=16, C=512, C8=64, H=W=64.
// ============================================================================

#define NT 256
#define NSLOT 296
#define NTILE 1024
#define SWB(o)  ((o) ^ (((o) >> 3) & 0x70))   // 128B-pitch swizzle
#define SW64(o) ((o) ^ (((o) >> 3) & 0x30))   // 64B-pitch swizzle

__device__ __half g_wh[640 * 512];
__device__ __half g_wl[640 * 512];
__device__ __half g_xh[16u * 64 * 512 * 64];
__device__ __half g_xl[16u * 64 * 512 * 64];

// SMEM layout (byte offsets from 1KB-aligned base):
//  ring: 3 stages x 24576.
//   QK stage (g<16):  +0 Whi[128][64B] SW64 (8K) | +8192 Wlo (8K)
//                     +16384 Xhi[32][128B] SW128 (4K) | +20480 Xlo (4K)
//   V stage (g>=16):  +0 Whi[128][128B] SW128 (16K) | +16384 Xhi[64][128B] (8K)
//  Q/K fp16 split @73728: Qhi(8K) Qlo(8K) Khi(8K) Klo(8K)
//    (VH fp16 [128][128B] 16K aliases Qhi+Qlo in phase 4;
//     softmax scratch 1K aliases Qhi after scores)
//  P: 106496: PH fp16 [64][128B] (8K)
#define STAGE 24576
#define Co    73728
#define QHo   73728
#define QLo   81920
#define KHo   90112
#define KLo   98304
#define PHo   106496
#define SMEM_BYTES (114688 + 1024)

__device__ __forceinline__ uint32_t smem_u32(const void* p) {
    uint32_t a;
    asm("{ .reg .u64 t; cvta.to.shared.u64 t, %1; cvt.u32.u64 %0, t; }"
        : "=r"(a) : "l"(p));
    return a;
}
__device__ __forceinline__ void cpasync16(uint32_t dst, const void* src) {
    asm volatile("cp.async.cg.shared.global [%0], [%1], 16;" :: "r"(dst), "l"(src));
}
__device__ __forceinline__ void cpcommit() {
    asm volatile("cp.async.commit_group;" ::: "memory");
}
__device__ __forceinline__ void cpwait1() {
    asm volatile("cp.async.wait_group 1;" ::: "memory");
}
__device__ __forceinline__ void cpwait0() {
    asm volatile("cp.async.wait_group 0;" ::: "memory");
}
__device__ __forceinline__ void ldsm_x4(uint32_t addr, uint32_t r[4]) {
    asm volatile("ldmatrix.sync.aligned.m8n8.x4.shared.b16 {%0,%1,%2,%3}, [%4];"
                 : "=r"(r[0]), "=r"(r[1]), "=r"(r[2]), "=r"(r[3]) : "r"(addr));
}
__device__ __forceinline__ void ldsm_x4t(uint32_t addr, uint32_t r[4]) {
    asm volatile("ldmatrix.sync.aligned.m8n8.x4.trans.shared.b16 {%0,%1,%2,%3}, [%4];"
                 : "=r"(r[0]), "=r"(r[1]), "=r"(r[2]), "=r"(r[3]) : "r"(addr));
}
__device__ __forceinline__ void mma_f16(float d[4], const uint32_t a[4],
                                        uint32_t b0, uint32_t b1) {
    asm volatile(
        "mma.sync.aligned.m16n8k16.row.col.f32.f16.f16.f32 "
        "{%0,%1,%2,%3}, {%4,%5,%6,%7}, {%8,%9}, {%0,%1,%2,%3};"
        : "+f"(d[0]), "+f"(d[1]), "+f"(d[2]), "+f"(d[3])
        : "r"(a[0]), "r"(a[1]), "r"(a[2]), "r"(a[3]), "r"(b0), "r"(b1));
}
__device__ __forceinline__ void split2(float a, float b, unsigned& hi, unsigned& lo) {
    __half ha = __float2half_rn(a), hb = __float2half_rn(b);
    float la = a - __half2float(ha);
    float lb = b - __half2float(hb);
    hi = (unsigned)__half_as_ushort(ha) | ((unsigned)__half_as_ushort(hb) << 16);
    lo = (unsigned)__half_as_ushort(__float2half_rn(la))
       | ((unsigned)__half_as_ushort(__float2half_rn(lb)) << 16);
}
__device__ __forceinline__ unsigned pack_half2(float a, float b) {
    return (unsigned)__half_as_ushort(__float2half_rn(a))
         | ((unsigned)__half_as_ushort(__float2half_rn(b)) << 16);
}

// A-fragment addr, 128B-pitch SW128 (non-trans A [m][k], or trans-B [k][n])
__device__ __forceinline__ uint32_t faddrA(uint32_t region, int row0, int colB, int lane) {
    int row = row0 + (lane & 7) + ((lane >> 3) & 1) * 8;
    int cb  = colB + ((lane >> 4) << 4);
    return region + SWB(row * 128 + cb);
}
// A-fragment addr, 64B-pitch SW64 (QK W buffers)
__device__ __forceinline__ uint32_t faddrW(uint32_t region, int row0, int colB, int lane) {
    int row = row0 + (lane & 7) + ((lane >> 3) & 1) * 8;
    int cb  = colB + ((lane >> 4) << 4);
    return region + SW64(row * 64 + cb);
}
// non-trans B from [n][k] (P), OR trans-A from [k][m] (Q): 128B pitch
__device__ __forceinline__ uint32_t faddrP(uint32_t region, int w0, int kB, int lane) {
    int row = w0 + (lane & 7) + ((lane >> 4) << 3);
    int cb  = kB + ((lane >> 3) & 1) * 16;
    return region + SWB(row * 128 + cb);
}

// ---------------------------------------------------------------------------
// merged prologue: blocks [0,32768) split x ; [32768,33088) split W
// ---------------------------------------------------------------------------
__global__ void __launch_bounds__(256, 4)
prep_kernel(const float* __restrict__ x,
            const float* __restrict__ Wq, const float* __restrict__ Wk,
            const float* __restrict__ Wv)
{
    if (blockIdx.x >= 32768) {
        int gid = (blockIdx.x - 32768) * 256 + threadIdx.x;
        int r = gid >> 7;
        int c = (gid & 127) * 4;
        const float* src = (r < 64)  ? (Wq + (size_t)r * 512 + c)
                         : (r < 128) ? (Wk + (size_t)(r - 64) * 512 + c)
                                     : (Wv + (size_t)(r - 128) * 512 + c);
        float4 v = *(const float4*)src;
        unsigned h0, l0, h1, l1;
        split2(v.x, v.y, h0, l0);
        split2(v.z, v.w, h1, l1);
        size_t off = (size_t)r * 512 + c;
        *(uint2*)(g_wh + off) = make_uint2(h0, h1);
        *(uint2*)(g_wl + off) = make_uint2(l0, l1);
    } else {
        size_t gid = (size_t)blockIdx.x * 256 + threadIdx.x;
        int w4 = (int)(gid & 15);
        size_t r = gid >> 4;
        int hh  = (int)(r & 63);
        size_t bc = r >> 6;
        int c  = (int)(bc & 511);
        int b  = (int)(bc >> 9);
        float4 v = *(const float4*)(x + gid * 4);
        unsigned h0, l0, h1, l1;
        split2(v.x, v.y, h0, l0);
        split2(v.z, v.w, h1, l1);
        size_t off = (((size_t)b * 64 + hh) * 512 + c) * 64 + w4 * 4;
        *(uint2*)(g_xh + off) = make_uint2(h0, h1);
        *(uint2*)(g_xl + off) = make_uint2(l0, l1);
    }
}

// ---------------------------------------------------------------------------
// issue stage g (0..47) of a tile; ring slot = g % 3 (continuous across tiles)
__device__ __forceinline__ void issueStage(uint32_t sb, int tile, int g, int t) {
    const __half* xh = g_xh + (size_t)tile * 32768;
    const __half* xl = g_xl + (size_t)tile * 32768;
    uint32_t stage = sb + (g % 3) * STAGE;
    if (g < 16) {
        int c0 = g * 32;
        #pragma unroll
        for (int j = t; j < 1024; j += NT) {
            int half = j >> 9;
            int u    = j & 511;
            int row  = u >> 2;
            int seg  = u & 3;
            const __half* src =
                (half ? g_wl : g_wh) + (size_t)row * 512 + c0 + seg * 8;
            cpasync16(stage + half * 8192 + SW64(row * 64 + seg * 16), src);
        }
        #pragma unroll
        for (int j = t; j < 512; j += NT) {
            int half = j >> 8;
            int u    = j & 255;
            int row  = u >> 3;
            int seg  = u & 7;
            const __half* src = (half ? xl : xh) + (size_t)(c0 + row) * 64 + seg * 8;
            cpasync16(stage + 16384 + half * 4096 + SWB(row * 128 + seg * 16), src);
        }
    } else {
        int local = g - 16;
        int Rb = 128 + (local >> 3) * 128;
        int c0 = (local & 7) * 64;
        #pragma unroll
        for (int j = t; j < 1024; j += NT) {
            int row = j >> 3;
            int seg = j & 7;
            cpasync16(stage + SWB(row * 128 + seg * 16),
                      g_wh + (size_t)(Rb + row) * 512 + c0 + seg * 8);
        }
        #pragma unroll
        for (int j = t; j < 512; j += NT) {
            int row = j >> 3;
            int seg = j & 7;
            cpasync16(stage + 16384 + SWB(row * 128 + seg * 16),
                      xh + (size_t)(c0 + row) * 64 + seg * 8);
        }
    }
    cpcommit();
}

// QK chunk (K=32), 3-pass fragment-reuse
__device__ __forceinline__ void mma_chunk_qk(uint32_t stage, int m0, int nB, int lane,
                                             float acc[2][4][4]) {
    uint32_t Xh = stage + 16384, Xl = stage + 20480;
    #pragma unroll
    for (int ks = 0; ks < 2; ks++) {
        uint32_t bH0[4], bH1[4], bL0[4], bL1[4], a[4];
        ldsm_x4t(faddrA(Xh, ks * 16, nB,      lane), bH0);
        ldsm_x4t(faddrA(Xh, ks * 16, nB + 32, lane), bH1);
        ldsm_x4t(faddrA(Xl, ks * 16, nB,      lane), bL0);
        ldsm_x4t(faddrA(Xl, ks * 16, nB + 32, lane), bL1);

        ldsm_x4(faddrW(stage, m0, ks * 32, lane), a);
        mma_f16(acc[0][0], a, bH0[0], bH0[1]);
        mma_f16(acc[0][1], a, bH0[2], bH0[3]);
        mma_f16(acc[0][2], a, bH1[0], bH1[1]);
        mma_f16(acc[0][3], a, bH1[2], bH1[3]);
        mma_f16(acc[0][0], a, bL0[0], bL0[1]);
        mma_f16(acc[0][1], a, bL0[2], bL0[3]);
        mma_f16(acc[0][2], a, bL1[0], bL1[1]);
        mma_f16(acc[0][3], a, bL1[2], bL1[3]);

        ldsm_x4(faddrW(stage, m0 + 16, ks * 32, lane), a);
        mma_f16(acc[1][0], a, bH0[0], bH0[1]);
        mma_f16(acc[1][1], a, bH0[2], bH0[3]);
        mma_f16(acc[1][2], a, bH1[0], bH1[1]);
        mma_f16(acc[1][3], a, bH1[2], bH1[3]);
        mma_f16(acc[1][0], a, bL0[0], bL0[1]);
        mma_f16(acc[1][1], a, bL0[2], bL0[3]);
        mma_f16(acc[1][2], a, bL1[0], bL1[1]);
        mma_f16(acc[1][3], a, bL1[2], bL1[3]);

        ldsm_x4(faddrW(stage + 8192, m0, ks * 32, lane), a);
        mma_f16(acc[0][0], a, bH0[0], bH0[1]);
        mma_f16(acc[0][1], a, bH0[2], bH0[3]);
        mma_f16(acc[0][2], a, bH1[0], bH1[1]);
        mma_f16(acc[0][3], a, bH1[2], bH1[3]);

        ldsm_x4(faddrW(stage + 8192, m0 + 16, ks * 32, lane), a);
        mma_f16(acc[1][0], a, bH0[0], bH0[1]);
        mma_f16(acc[1][1], a, bH0[2], bH0[3]);
        mma_f16(acc[1][2], a, bH1[0], bH1[1]);
        mma_f16(acc[1][3], a, bH1[2], bH1[3]);
    }
}

// V chunk (K=64), 1-pass: Whi x Xhi
__device__ __forceinline__ void mma_chunk_v64(uint32_t stage, int m0, int nB, int lane,
                                              float acc[2][4][4]) {
    uint32_t Xh = stage + 16384;
    #pragma unroll
    for (int ks = 0; ks < 4; ks++) {
        uint32_t bH0[4], bH1[4], a[4];
        ldsm_x4t(faddrA(Xh, ks * 16, nB,      lane), bH0);
        ldsm_x4t(faddrA(Xh, ks * 16, nB + 32, lane), bH1);

        ldsm_x4(faddrA(stage, m0, ks * 32, lane), a);
        mma_f16(acc[0][0], a, bH0[0], bH0[1]);
        mma_f16(acc[0][1], a, bH0[2], bH0[3]);
        mma_f16(acc[0][2], a, bH1[0], bH1[1]);
        mma_f16(acc[0][3], a, bH1[2], bH1[3]);

        ldsm_x4(faddrA(stage, m0 + 16, ks * 32, lane), a);
        mma_f16(acc[1][0], a, bH0[0], bH0[1]);
        mma_f16(acc[1][1], a, bH0[2], bH0[3]);
        mma_f16(acc[1][2], a, bH1[0], bH1[1]);
        mma_f16(acc[1][3], a, bH1[2], bH1[3]);
    }
}

// ---------------------------------------------------------------------------
// main persistent kernel: grid 296, 256 threads, 2 CTAs/SM
// ---------------------------------------------------------------------------
extern "C" __global__ void __launch_bounds__(NT, 2)
axial_attn_kernel(const float* __restrict__ bq, const float* __restrict__ bk,
                  const float* __restrict__ bv,
                  const float* __restrict__ relh, const float* __restrict__ relw,
                  float* __restrict__ out)
{
    extern __shared__ char smraw[];
    char* smb = (char*)(((uintptr_t)smraw + 1023) & ~(uintptr_t)1023);
    const uint32_t sb = smem_u32(smb);

    const uint32_t PH = sb + PHo;
    const uint32_t VH = sb + Co;

    const int t    = threadIdx.x;
    const int wid  = t >> 5;
    const int lane = t & 31;
    const int m0   = (wid >> 1) * 32;   // warp m-tile (phases 1/4)
    const int wn   = wid & 1;           // warp n-tile
    const int nB   = wn * 64;
    const int wm   = wid >> 1;          // scores m(w)-tile (16 rows)

    issueStage(sb, blockIdx.x, 0, t);
    issueStage(sb, blockIdx.x, 1, t);

    for (int tile = blockIdx.x; tile < NTILE; tile += NSLOT) {
        const int hRow = tile & 63;
        const int b    = tile >> 6;
        const bool lastTile = (tile + NSLOT >= NTILE);

        // ---- Phase 1: QK projection, stages 0..15 ----
        float acc[2][4][4];
        #pragma unroll
        for (int i = 0; i < 2; i++)
            #pragma unroll
            for (int j = 0; j < 4; j++)
                #pragma unroll
                for (int e = 0; e < 4; e++) acc[i][j][e] = 0.f;

        for (int g = 0; g < 16; g++) {
            cpwait1();
            __syncthreads();
            issueStage(sb, tile, g + 2, t);
            mma_chunk_qk(sb + (g % 3) * STAGE, m0, nB, lane, acc);
        }

        // epilogue: bias + rel -> Q/K fp16 hi/lo, [c][w]/[c][v] SW128
        #pragma unroll
        for (int mi = 0; mi < 2; mi++) {
            #pragma unroll
            for (int nj = 0; nj < 4; nj++) {
                int row = m0 + mi * 16 + (lane >> 2);
                int col = wn * 32 + nj * 8 + (lane & 3) * 2;
                float d0 = acc[mi][nj][0], d1 = acc[mi][nj][1];
                float d2 = acc[mi][nj][2], d3 = acc[mi][nj][3];
                unsigned h, l;
                if (row < 64) {
                    float a  = bq[row] + relh[(size_t)row * 512 + hRow];
                    float a2 = bq[row + 8] + relh[(size_t)(row + 8) * 512 + hRow];
                    split2(d0 + a, d1 + a, h, l);
                    *(unsigned*)(smb + QHo + SWB(row * 128 + col * 2)) = h;
                    *(unsigned*)(smb + QLo + SWB(row * 128 + col * 2)) = l;
                    split2(d2 + a2, d3 + a2, h, l);
                    *(unsigned*)(smb + QHo + SWB((row + 8) * 128 + col * 2)) = h;
                    *(unsigned*)(smb + QLo + SWB((row + 8) * 128 + col * 2)) = l;
                } else {
                    int ok = row - 64;
                    float b1 = bk[ok], b2 = bk[ok + 8];
                    split2(d0 + b1 + relw[(size_t)ok * 512 + col],
                           d1 + b1 + relw[(size_t)ok * 512 + col + 1], h, l);
                    *(unsigned*)(smb + KHo + SWB(ok * 128 + col * 2)) = h;
                    *(unsigned*)(smb + KLo + SWB(ok * 128 + col * 2)) = l;
                    split2(d2 + b2 + relw[(size_t)(ok + 8) * 512 + col],
                           d3 + b2 + relw[(size_t)(ok + 8) * 512 + col + 1], h, l);
                    *(unsigned*)(smb + KHo + SWB((ok + 8) * 128 + col * 2)) = h;
                    *(unsigned*)(smb + KLo + SWB((ok + 8) * 128 + col * 2)) = l;
                }
            }
        }
        __syncthreads();

        // ---- Phase 2+3: scores via HMMA 3-pass + fragment softmax ----
        {
            float sc[4][4];
            #pragma unroll
            for (int i = 0; i < 4; i++)
                #pragma unroll
                for (int j = 0; j < 4; j++) sc[i][j] = 0.f;

            #pragma unroll
            for (int kt = 0; kt < 4; kt++) {
                int k0 = kt * 16;
                uint32_t aH[4], aL[4], bH0[4], bH1[4], bL0[4], bL1[4];
                ldsm_x4t(faddrP(sb + QHo, k0, wm * 32, lane), aH);   // trans-A
                ldsm_x4t(faddrP(sb + QLo, k0, wm * 32, lane), aL);
                ldsm_x4t(faddrA(sb + KHo, k0, wn * 64,      lane), bH0);
                ldsm_x4t(faddrA(sb + KHo, k0, wn * 64 + 32, lane), bH1);
                ldsm_x4t(faddrA(sb + KLo, k0, wn * 64,      lane), bL0);
                ldsm_x4t(faddrA(sb + KLo, k0, wn * 64 + 32, lane), bL1);
                mma_f16(sc[0], aH, bH0[0], bH0[1]);
                mma_f16(sc[1], aH, bH0[2], bH0[3]);
                mma_f16(sc[2], aH, bH1[0], bH1[1]);
                mma_f16(sc[3], aH, bH1[2], bH1[3]);
                mma_f16(sc[0], aH, bL0[0], bL0[1]);
                mma_f16(sc[1], aH, bL0[2], bL0[3]);
                mma_f16(sc[2], aH, bL1[0], bL1[1]);
                mma_f16(sc[3], aH, bL1[2], bL1[3]);
                mma_f16(sc[0], aL, bH0[0], bH0[1]);
                mma_f16(sc[1], aL, bH0[2], bH0[3]);
                mma_f16(sc[2], aL, bH1[0], bH1[1]);
                mma_f16(sc[3], aL, bH1[2], bH1[3]);
            }
            __syncthreads();   // all Q/K ldsm done; Qhi region becomes scratch

            float* rmax = (float*)(smb + Co);          // [64][2]
            float* rsum = (float*)(smb + Co + 512);    // [64][2]
            int r0 = wm * 16 + (lane >> 2);
            int r1 = r0 + 8;

            float m0v = sc[0][0], m1v = sc[0][2];
            #pragma unroll
            for (int nb = 0; nb < 4; nb++) {
                m0v = fmaxf(m0v, fmaxf(sc[nb][0], sc[nb][1]));
                m1v = fmaxf(m1v, fmaxf(sc[nb][2], sc[nb][3]));
            }
            #pragma unroll
            for (int off = 1; off <= 2; off <<= 1) {
                m0v = fmaxf(m0v, __shfl_xor_sync(0xffffffffu, m0v, off));
                m1v = fmaxf(m1v, __shfl_xor_sync(0xffffffffu, m1v, off));
            }
            if ((lane & 3) == 0) {
                rmax[r0 * 2 + wn] = m0v;
                rmax[r1 * 2 + wn] = m1v;
            }
            __syncthreads();
            m0v = fmaxf(rmax[r0 * 2], rmax[r0 * 2 + 1]);
            m1v = fmaxf(rmax[r1 * 2], rmax[r1 * 2 + 1]);

            float s0 = 0.f, s1 = 0.f;
            #pragma unroll
            for (int nb = 0; nb < 4; nb++) {
                sc[nb][0] = __expf(sc[nb][0] - m0v);
                sc[nb][1] = __expf(sc[nb][1] - m0v);
                sc[nb][2] = __expf(sc[nb][2] - m1v);
                sc[nb][3] = __expf(sc[nb][3] - m1v);
                s0 += sc[nb][0] + sc[nb][1];
                s1 += sc[nb][2] + sc[nb][3];
            }
            #pragma unroll
            for (int off = 1; off <= 2; off <<= 1) {
                s0 += __shfl_xor_sync(0xffffffffu, s0, off);
                s1 += __shfl_xor_sync(0xffffffffu, s1, off);
            }
            if ((lane & 3) == 0) {
                rsum[r0 * 2 + wn] = s0;
                rsum[r1 * 2 + wn] = s1;
            }
            __syncthreads();
            float i0 = 1.f / (rsum[r0 * 2] + rsum[r0 * 2 + 1]);
            float i1 = 1.f / (rsum[r1 * 2] + rsum[r1 * 2 + 1]);

            #pragma unroll
            for (int nb = 0; nb < 4; nb++) {
                int col = wn * 32 + nb * 8 + (lane & 3) * 2;
                *(unsigned*)(smb + PHo + SWB(r0 * 128 + col * 2)) =
                    pack_half2(sc[nb][0] * i0, sc[nb][1] * i0);
                *(unsigned*)(smb + PHo + SWB(r1 * 128 + col * 2)) =
                    pack_half2(sc[nb][2] * i1, sc[nb][3] * i1);
            }
        }

        // ---- Phase 4: V projection (K=64 stages) + AV, stages 16..47 ----
        for (int g = 16; g < 48; g++) {
            int local = g - 16;
            int kc = local & 7;
            if (kc == 0) {
                float* va = &acc[0][0][0];
                #pragma unroll
                for (int i = 0; i < 32; i++) va[i] = 0.f;
            }
            if (lastTile && g == 47) cpwait0(); else cpwait1();
            __syncthreads();
            {
                int n = g + 2;
                if (n < 48)         issueStage(sb, tile, n, t);
                else if (!lastTile) issueStage(sb, tile + NSLOT, n - 48, t);
            }
            mma_chunk_v64(sb + (g % 3) * STAGE, m0, nB, lane, acc);

            if (kc == 7) {
                int dc = local >> 3;
                #pragma unroll
                for (int mi = 0; mi < 2; mi++) {
                    #pragma unroll
                    for (int nj = 0; nj < 4; nj++) {
                        int row = m0 + mi * 16 + (lane >> 2);
                        int col = wn * 32 + nj * 8 + (lane & 3) * 2;
                        float b0f = bv[dc * 128 + row];
                        float b1f = bv[dc * 128 + row + 8];
                        unsigned h0 = pack_half2(acc[mi][nj][0] + b0f, acc[mi][nj][1] + b0f);
                        unsigned h1 = pack_half2(acc[mi][nj][2] + b1f, acc[mi][nj][3] + b1f);
                        *(unsigned*)(smb + Co + SWB(row * 128 + col * 2))       = h0;
                        *(unsigned*)(smb + Co + SWB((row + 8) * 128 + col * 2)) = h1;
                    }
                }
                __syncthreads();

                float oac[2][4][4];
                #pragma unroll
                for (int i = 0; i < 2; i++)
                    #pragma unroll
                    for (int j = 0; j < 4; j++)
                        #pragma unroll
                        for (int e = 0; e < 4; e++) oac[i][j][e] = 0.f;

                #pragma unroll
                for (int k = 0; k < 4; k++) {
                    uint32_t p0h[4], p1h[4], a[4];
                    ldsm_x4(faddrP(PH, wn * 32,      k * 32, lane), p0h);
                    ldsm_x4(faddrP(PH, wn * 32 + 16, k * 32, lane), p1h);

                    ldsm_x4(faddrA(VH, m0, k * 32, lane), a);
                    mma_f16(oac[0][0], a, p0h[0], p0h[1]);
                    mma_f16(oac[0][1], a, p0h[2], p0h[3]);
                    mma_f16(oac[0][2], a, p1h[0], p1h[1]);
                    mma_f16(oac[0][3], a, p1h[2], p1h[3]);

                    ldsm_x4(faddrA(VH, m0 + 16, k * 32, lane), a);
                    mma_f16(oac[1][0], a, p0h[0], p0h[1]);
                    mma_f16(oac[1][1], a, p0h[2], p0h[3]);
                    mma_f16(oac[1][2], a, p1h[0], p1h[1]);
                    mma_f16(oac[1][3], a, p1h[2], p1h[3]);
                }

                #pragma unroll
                for (int mi = 0; mi < 2; mi++) {
                    #pragma unroll
                    for (int nj = 0; nj < 4; nj++) {
                        int row = m0 + mi * 16 + (lane >> 2);
                        int col = wn * 32 + nj * 8 + (lane & 3) * 2;
                        size_t base0 = (((size_t)b * 512 + dc * 128 + row) * 64 + hRow) * 64 + col;
                        size_t base1 = base0 + 8 * 4096;
                        *(float2*)&out[base0] = make_float2(oac[mi][nj][0], oac[mi][nj][1]);
                        *(float2*)&out[base1] = make_float2(oac[mi][nj][2], oac[mi][nj][3]);
                    }
                }
            }
        }
    }
}

extern "C" void kernel_launch(void* const* d_in, const int* in_sizes, int n_in,
                              void* d_out, int out_size)
{
    const float* x    = (const float*)d_in[0];
    const float* Wq   = (const float*)d_in[1];
    const float* bq   = (const float*)d_in[2];
    const float* Wk   = (const float*)d_in[3];
    const float* bk   = (const float*)d_in[4];
    const float* Wv   = (const float*)d_in[5];
    const float* bv   = (const float*)d_in[6];
    const float* relh = (const float*)d_in[7];
    const float* relw = (const float*)d_in[8];
    float* out = (float*)d_out;

    cudaFuncSetAttribute(axial_attn_kernel,
                         cudaFuncAttributeMaxDynamicSharedMemorySize, SMEM_BYTES);

    prep_kernel<<<33088, 256>>>(x, Wq, Wk, Wv);
    axial_attn_kernel<<<NSLOT, NT, SMEM_BYTES>>>(bq, bk, bv, relh, relw, out);
}